// round 15
// baseline (speedup 1.0000x reference)
#include <cuda_runtime.h>
#include <cuda_bf16.h>
#include <math.h>
#include <stdint.h>

#define LSEQ 2048
#define NZ 4            // (branch, batch) pairs: z = br*2 + b
#define NCH 16          // scan chunks
#define TCH 128         // t per chunk

typedef unsigned long long u64;

// ---------------- scratch (device globals; no runtime allocation) ----------
__device__ float g_xz  [NZ * 512 * LSEQ];       // in_proj output [z][512][L]
__device__ float g_xc  [NZ * 256 * LSEQ];       // silu(conv(x)) fp32 (scan u)
__device__ float g_xdbl[NZ * 288 * LSEQ];       // x_proj output [z][288][L]
__device__ float g_A   [2 * 256 * 128];         // A1, A2
__device__ float g_maxes[8] = {
    -INFINITY, -INFINITY, -INFINITY, -INFINITY,
    -INFINITY, -INFINITY, -INFINITY, -INFINITY};
__device__ float g_D1  [2 * 256];
__device__ int   g_lin [2 * 256];

// chunked-scan intermediates
__device__ float g_dl  [NZ * 256 * LSEQ];       // delta
__device__ float g_ys  [NZ * 256 * LSEQ];       // local y (incl. u*D)
__device__ float g_hloc[NZ * NCH * 256 * 128];  // chunk-final local states
__device__ float g_hin [NZ * NCH * 256 * 128];  // chunk entry states
__device__ float g_Ss  [NZ * 256 * NCH];        // per-chunk sum of delta

// packed bf16 hi/lo operand planes  [plane][...]
__device__ uint32_t g_w2in [2][2][512 * 256];   // [br][plane][m*KP+kp]
__device__ uint32_t g_w2xp [2][2][288 * 128];
__device__ uint32_t g_w2out[2][2][512 * 256];
__device__ uint32_t g_inp2 [2][NZ][256 * 2048]; // [plane][z][kp*L+l]
__device__ uint32_t g_xc2  [2][NZ][128 * 2048];
__device__ uint32_t g_y2   [2][NZ][256 * 2048];

// ---------------- f32x2 packed helpers (scan) --------------------------------
__device__ __forceinline__ u64 pk2(float x, float y) {
    u64 r; asm("mov.b64 %0, {%1, %2};" : "=l"(r) : "f"(x), "f"(y)); return r;
}
__device__ __forceinline__ void upk2(u64 v, float& x, float& y) {
    asm("mov.b64 {%0, %1}, %2;" : "=f"(x), "=f"(y) : "l"(v));
}
__device__ __forceinline__ u64 fma2(u64 a, u64 b, u64 c) {
    u64 d; asm("fma.rn.f32x2 %0, %1, %2, %3;" : "=l"(d) : "l"(a), "l"(b), "l"(c));
    return d;
}
__device__ __forceinline__ u64 mul2(u64 a, u64 b) {
    u64 d; asm("mul.rn.f32x2 %0, %1, %2;" : "=l"(d) : "l"(a), "l"(b));
    return d;
}

// ---------------- scalar helpers ---------------------------------------------
#define LOG2EF 1.4426950408889634f
#define RLOG2EF 0.6931471805599453f
__device__ __forceinline__ float ex2f(float x) {
    float r; asm("ex2.approx.f32 %0, %1;" : "=f"(r) : "f"(x)); return r;
}
__device__ __forceinline__ float lg2f(float x) {
    float r; asm("lg2.approx.f32 %0, %1;" : "=f"(r) : "f"(x)); return r;
}
__device__ __forceinline__ float fexpf(float x) { return ex2f(x * LOG2EF); }
__device__ __forceinline__ float spf(float v, float thr) {
    float a = fabsf(v) - thr;
    a = a > 0.f ? a : 0.f;
    return (v > 0.f) ? a : (v < 0.f ? -a : 0.f);
}
__device__ __forceinline__ float siluf(float v) {
    return v / (1.f + ex2f(-v * LOG2EF));
}
__device__ __forceinline__ float softplusf(float v) {
    // max(v,0) + ln(1 + exp(-|v|)); stable both tails, MUFU-based
    float t = ex2f(-fabsf(v) * LOG2EF);
    return fmaxf(v, 0.f) + lg2f(1.f + t) * RLOG2EF;
}
__device__ __forceinline__ float negInf() { return __int_as_float(0xff800000); }

__device__ float blockReduceMax(float v) {
    __shared__ float sh[32];
    __syncthreads();
    #pragma unroll
    for (int o = 16; o; o >>= 1) v = fmaxf(v, __shfl_xor_sync(0xffffffffu, v, o));
    if ((threadIdx.x & 31) == 0) sh[threadIdx.x >> 5] = v;
    __syncthreads();
    float r = negInf();
    if (threadIdx.x < (blockDim.x >> 5)) r = sh[threadIdx.x];
    if ((threadIdx.x >> 5) == 0) {
        #pragma unroll
        for (int o = 16; o; o >>= 1) r = fmaxf(r, __shfl_xor_sync(0xffffffffu, r, o));
        if (threadIdx.x == 0) sh[0] = r;
    }
    __syncthreads();
    return sh[0];
}

__device__ __forceinline__ void atomicMaxFloatCAS(float* addr, float val) {
    int* ai = (int*)addr;
    int old = *ai;
    while (__int_as_float(old) < val) {
        int assumed = old;
        old = atomicCAS(ai, assumed, __float_as_int(val));
        if (old == assumed) break;
    }
}

// ---------------- bf16 helpers -------------------------------------------------
__device__ __forceinline__ uint32_t bfpair(float x, float y) {
    __nv_bfloat162 h = __floats2bfloat162_rn(x, y);
    return *reinterpret_cast<uint32_t*>(&h);
}
__device__ __forceinline__ float bf16val(float x) {
    __nv_bfloat16 h = __float2bfloat16_rn(x);
    return __bfloat162float(h);
}

__device__ __forceinline__ void mma_bf16(float* d, const uint32_t* a, const uint32_t* b) {
    asm volatile(
        "mma.sync.aligned.m16n8k16.row.col.f32.bf16.bf16.f32 "
        "{%0,%1,%2,%3}, {%4,%5,%6,%7}, {%8,%9}, {%0,%1,%2,%3};"
        : "+f"(d[0]), "+f"(d[1]), "+f"(d[2]), "+f"(d[3])
        : "r"(a[0]), "r"(a[1]), "r"(a[2]), "r"(a[3]), "r"(b[0]), "r"(b[1]));
}

__device__ __forceinline__ void ldm_x4(uint32_t* r, uint32_t addr) {
    asm volatile(
        "ldmatrix.sync.aligned.m8n8.x4.shared.b16 {%0,%1,%2,%3}, [%4];"
        : "=r"(r[0]), "=r"(r[1]), "=r"(r[2]), "=r"(r[3]) : "r"(addr));
}

__device__ __forceinline__ uint32_t smem_u32(const void* p) {
    uint32_t a;
    asm("{ .reg .u64 t; cvta.to.shared.u64 t, %1; cvt.u32.u64 %0, t; }"
        : "=r"(a) : "l"(p));
    return a;
}
__device__ __forceinline__ void cpa16(uint32_t dst, const void* src) {
    asm volatile("cp.async.cg.shared.global [%0], [%1], 16;" :: "r"(dst), "l"(src));
}
#define CP_COMMIT() asm volatile("cp.async.commit_group;" ::: "memory")
#define CP_WAIT1()  asm volatile("cp.async.wait_group 1;" ::: "memory")
#define CP_WAIT0()  asm volatile("cp.async.wait_group 0;" ::: "memory")

// ---------------- weight conversion + prepA A-max (launch 1) ------------------
__global__ void cvt_w_m1(const float* __restrict__ inw,  const float* __restrict__ inw2,
                         const float* __restrict__ xpw,  const float* __restrict__ xpw2,
                         const float* __restrict__ ow,   const float* __restrict__ ow2,
                         const float* __restrict__ Alog, const float* __restrict__ eps) {
    int s = blockIdx.y;
    if (s == 6) {
        if (blockIdx.x >= 64) return;
        float e = 1.f + eps[0];
        float m = negInf();
        for (int i = blockIdx.x * blockDim.x + threadIdx.x; i < 256 * 128;
             i += 64 * blockDim.x)
            m = fmaxf(m, -e * fexpf(Alog[i]));
        m = blockReduceMax(m);
        if (threadIdx.x == 0) atomicMaxFloatCAS(&g_maxes[6], m);
        return;
    }
    int e = blockIdx.x * 256 + threadIdx.x;
    const float* src; uint32_t* dhi; uint32_t* dlo; int KP, total;
    if (s < 2)      { src = s        ? inw2 : inw; dhi = g_w2in [s][0];     dlo = g_w2in [s][1];     KP = 256; total = 512 * 256; }
    else if (s < 4) { src = (s - 2)  ? xpw2 : xpw; dhi = g_w2xp [s - 2][0]; dlo = g_w2xp [s - 2][1]; KP = 128; total = 288 * 128; }
    else            { src = (s - 4)  ? ow2  : ow;  dhi = g_w2out[s - 4][0]; dlo = g_w2out[s - 4][1]; KP = 256; total = 512 * 256; }
    if (e >= total) return;
    int m = e / KP, kp = e - m * KP;
    float v0 = src[(long)m * (KP * 2) + 2 * kp];
    float v1 = src[(long)m * (KP * 2) + 2 * kp + 1];
    float h0 = bf16val(v0), h1 = bf16val(v1);
    dhi[e] = bfpair(h0, h1);
    dlo[e] = bfpair(v0 - h0, v1 - h1);
}

// ---------------- input conversion + prepA stage 1 (launch 2) -----------------
__global__ void cvt_inp_s1(const float* __restrict__ inp,
                           const float* __restrict__ Alog,
                           const float* __restrict__ eps) {
    int bk = blockIdx.x;
    if (bk >= 8192) {
        int bx = bk - 8192;
        float e = 1.f + eps[0];
        float thr1 = 0.1f * g_maxes[6];
        float m = negInf();
        for (int i = bx * blockDim.x + threadIdx.x; i < 256 * 128;
             i += 64 * blockDim.x) {
            float a1 = spf(-e * fexpf(Alog[i]), thr1);
            g_A[i] = a1;
            m = fmaxf(m, a1);
        }
        m = blockReduceMax(m);
        if (threadIdx.x == 0) atomicMaxFloatCAS(&g_maxes[7], m);
        return;
    }
    long idx = (long)bk * blockDim.x + threadIdx.x;
    int l  = (int)(idx & 2047);
    int kp = (int)((idx >> 11) & 255);
    int z  = (int)(idx >> 19);
    int br = z >> 1, b = z & 1;
    const float* p = inp + ((long)b * 1024 + br * 512 + 2 * kp) * LSEQ + l;
    float v0 = p[0], v1 = p[LSEQ];
    float h0 = bf16val(v0), h1 = bf16val(v1);
    long off = (long)kp * LSEQ + l;
    g_inp2[0][z][off] = bfpair(h0, h1);
    g_inp2[1][z][off] = bfpair(v0 - h0, v1 - h1);
}

// ---------------- bf16-split tensor GEMM: 3-stage cp.async, 1 sync/chunk ------
#define G_SMEM_BYTES ((9216 + 6528) * 4)
template <int EPI>
__global__ void __launch_bounds__(256) gemm_cp(
    const uint32_t* __restrict__ W2, long wbr, long wpl, int KP,
    const uint32_t* __restrict__ B2, long bz, long bpl,
    float* __restrict__ C, long csz, int ldC, int M)
{
    extern __shared__ __align__(16) uint32_t smemU[];

    int z = blockIdx.z, br = z >> 1;
    const uint32_t* Wp = W2 + (long)br * wbr;
    const uint32_t* Bp = B2 + (long)z * bz;
    float*          Cp = C + (long)z * csz;
    int m0 = blockIdx.y * 128, n0 = blockIdx.x * 128;

    int tid = threadIdx.x;
    int wid = tid >> 5, lane = tid & 31;
    int g = lane >> 2, t = lane & 3;
    int wm = (wid >> 2) * 64;
    int wn = (wid & 3) * 32;

    int arow = tid >> 1, aseg = tid & 1;
    int am = m0 + arow; if (am >= M) am = M - 1;
    const uint32_t* aptr = Wp + (long)am * KP + aseg * 4;
    int bkp = tid >> 5, bseg = tid & 31;
    const uint32_t* bptr = Bp + (long)bkp * LSEQ + n0 + bseg * 4;

    uint32_t sAb = smem_u32(smemU);
    uint32_t sBb = sAb + 9216 * 4;
    uint32_t ldmOff = (uint32_t)((lane & 15) * 48 + (lane >> 4) * 16);

    float acc[4][4][4];
    #pragma unroll
    for (int i = 0; i < 4; i++)
        #pragma unroll
        for (int j = 0; j < 4; j++)
            #pragma unroll
            for (int q = 0; q < 4; q++) acc[i][j][q] = 0.f;

    const int NC = KP >> 3;

    auto issue = [&](int ic) {
        int buf = ic % 3;
        int kp0 = ic << 3;
        #pragma unroll
        for (int pl = 0; pl < 2; pl++) {
            cpa16(sAb + (uint32_t)(((buf * 2 + pl) * 1536 + arow * 12 + aseg * 4) * 4),
                  aptr + (long)pl * wpl + kp0);
            cpa16(sBb + (uint32_t)(((buf * 2 + pl) * 1088 + bkp * 136 + bseg * 4) * 4),
                  bptr + (long)pl * bpl + (long)kp0 * LSEQ);
        }
        CP_COMMIT();
    };

    issue(0);
    if (NC > 1) issue(1);

    for (int ic = 0; ic < NC; ic++) {
        if (ic + 1 < NC) { CP_WAIT1(); } else { CP_WAIT0(); }
        __syncthreads();
        if (ic + 2 < NC) issue(ic + 2);

        int s = ic % 3;
        const uint32_t* B0 = smemU + 9216 + (s * 2 + 0) * 1088;
        const uint32_t* B1 = smemU + 9216 + (s * 2 + 1) * 1088;
        uint32_t aHi = sAb + (uint32_t)((s * 2 + 0) * 1536 * 4) + (uint32_t)(wm * 48) + ldmOff;
        uint32_t aLo = sAb + (uint32_t)((s * 2 + 1) * 1536 * 4) + (uint32_t)(wm * 48) + ldmOff;

        uint32_t rbh[4][2], rbl[4][2];
        #pragma unroll
        for (int j = 0; j < 4; j++) {
            int nb = wn + 8 * j + g;
            rbh[j][0] = B0[t * 136 + nb];
            rbh[j][1] = B0[(t + 4) * 136 + nb];
            rbl[j][0] = B1[t * 136 + nb];
            rbl[j][1] = B1[(t + 4) * 136 + nb];
        }
        #pragma unroll
        for (int i = 0; i < 4; i++) {
            uint32_t rah[4], ral[4];
            ldm_x4(rah, aHi + (uint32_t)(i * 16 * 48));
            ldm_x4(ral, aLo + (uint32_t)(i * 16 * 48));
            #pragma unroll
            for (int j = 0; j < 4; j++) {
                mma_bf16(acc[i][j], rah, rbh[j]);
                mma_bf16(acc[i][j], rah, rbl[j]);
                mma_bf16(acc[i][j], ral, rbh[j]);
            }
        }
    }
    __syncthreads();

    if constexpr (EPI == 1) {
        float* sT = (float*)smemU;
        #pragma unroll
        for (int q = 0; q < 4; q++) {
            __syncthreads();
            if ((wid & 3) == q) {
                #pragma unroll
                for (int i = 0; i < 4; i++) {
                    #pragma unroll
                    for (int j = 0; j < 4; j++) {
                        int lloc = 8 * j + 2 * t;
                        int m1 = wm + 16 * i + g;
                        sT[lloc * 132 + m1]           = acc[i][j][0];
                        sT[(lloc + 1) * 132 + m1]     = acc[i][j][1];
                        sT[lloc * 132 + m1 + 8]       = acc[i][j][2];
                        sT[(lloc + 1) * 132 + m1 + 8] = acc[i][j][3];
                    }
                }
            }
            __syncthreads();
            int lloc = tid >> 3;
            int seg  = (tid & 7) * 16;
            long lg = n0 + q * 32 + lloc;
            float4*       dst  = (float4*)&Cp[lg * ldC + m0 + seg];
            const float4* srcp = (const float4*)&sT[lloc * 132 + seg];
            dst[0] = srcp[0]; dst[1] = srcp[1];
            dst[2] = srcp[2]; dst[3] = srcp[3];
        }
    } else {
        float mB = negInf(), mC = negInf();
        #pragma unroll
        for (int i = 0; i < 4; i++) {
            int m1 = m0 + wm + 16 * i + g;
            int m2 = m1 + 8;
            bool ok1 = m1 < M, ok2 = m2 < M;
            float r1mx = negInf(), r2mx = negInf();
            #pragma unroll
            for (int j = 0; j < 4; j++) {
                int l0 = n0 + wn + 8 * j + 2 * t;
                if (ok1) {
                    *(float2*)&Cp[(long)m1 * ldC + l0] =
                        make_float2(acc[i][j][0], acc[i][j][1]);
                    r1mx = fmaxf(r1mx, fmaxf(acc[i][j][0], acc[i][j][1]));
                }
                if (ok2) {
                    *(float2*)&Cp[(long)m2 * ldC + l0] =
                        make_float2(acc[i][j][2], acc[i][j][3]);
                    r2mx = fmaxf(r2mx, fmaxf(acc[i][j][2], acc[i][j][3]));
                }
            }
            if (EPI == 3) {
                if (ok1) {
                    if (m1 >= 32 && m1 < 160) mB = fmaxf(mB, r1mx);
                    else if (m1 >= 160)       mC = fmaxf(mC, r1mx);
                }
                if (ok2) {
                    if (m2 >= 32 && m2 < 160) mB = fmaxf(mB, r2mx);
                    else if (m2 >= 160)       mC = fmaxf(mC, r2mx);
                }
            }
        }
        if (EPI == 3) {
            #pragma unroll
            for (int o = 16; o; o >>= 1) {
                mB = fmaxf(mB, __shfl_xor_sync(0xffffffffu, mB, o));
                mC = fmaxf(mC, __shfl_xor_sync(0xffffffffu, mC, o));
            }
            if (lane == 0) {
                if (mB > negInf()) atomicMaxFloatCAS(&g_maxes[2 + br], mB);
                if (mC > negInf()) atomicMaxFloatCAS(&g_maxes[4 + br], mC);
            }
        }
    }
}

// ---------------- conv + silu (+ fused prepA stage 2/affine) ------------------
__global__ void conv_silu2(const float* __restrict__ cxw0, const float* __restrict__ czw0,
                           const float* __restrict__ cxw1, const float* __restrict__ czw1) {
    int bk = blockIdx.x;
    if (bk >= 4096) {
        float thr2 = 0.1f * g_maxes[7];
        const int N = 256 * 128;
        int bx = bk - 4096;
        if (bx < 64) {
            for (int i = bx * blockDim.x + threadIdx.x; i < N;
                 i += 64 * blockDim.x)
                g_A[N + i] = spf(g_A[i], thr2);
            return;
        }
        int idx = (bx - 64) * blockDim.x + threadIdx.x;
        if (idx >= 512) return;
        bool isA2 = idx >= 256;
        const float* row = g_A + (long)(isA2 ? (idx - 256) : idx) * 128;
        float vprev = isA2 ? spf(row[0], thr2) : row[0];
        float v32   = isA2 ? spf(row[32], thr2) : row[32];
        float d1 = (v32 - vprev) * (1.f / 32.f);
        bool ok = true;
        for (int n = 1; n < 128; n++) {
            float v = isA2 ? spf(row[n], thr2) : row[n];
            ok = ok && (fabsf((v - vprev) - d1) <= 2e-4f);
            vprev = v;
        }
        g_D1[idx] = d1;
        g_lin[idx] = ok ? 1 : 0;
        return;
    }
    long idx = (long)bk * blockDim.x + threadIdx.x;
    int l = (int)(idx & 2047);
    int p = (int)((idx >> 11) & 127);
    int z = (int)(idx >> 18);
    int br = z >> 1;
    const float* cxw = br ? cxw1 : cxw0;
    const float* czw = br ? czw1 : czw0;
    float sx[2], sz[2];
    #pragma unroll
    for (int q = 0; q < 2; q++) {
        int d = 2 * p + q;
        const float* wx = cxw + d * 4;
        const float* wz = czw + d * 4;
        const float* xrow = g_xz + ((long)z * 512 + d) * LSEQ;
        const float* zrow = g_xz + ((long)z * 512 + 256 + d) * LSEQ;
        float ax = 0.f, az = 0.f;
        #pragma unroll
        for (int j = 0; j < 4; j++) {
            int ll = l + j - 1;
            if (ll >= 0 && ll < LSEQ) {
                ax = fmaf(wx[j], xrow[ll], ax);
                az = fmaf(wz[j], zrow[ll], az);
            }
        }
        sx[q] = siluf(ax);
        sz[q] = siluf(az);
        g_xc[((long)z * 256 + d) * LSEQ + l] = sx[q];
    }
    long off = (long)p * LSEQ + l;
    float hx0 = bf16val(sx[0]), hx1 = bf16val(sx[1]);
    g_xc2[0][z][off] = bfpair(hx0, hx1);
    g_xc2[1][z][off] = bfpair(sx[0] - hx0, sx[1] - hx1);
    float hz0 = bf16val(sz[0]), hz1 = bf16val(sz[1]);
    long offy = (long)(128 + p) * LSEQ + l;
    g_y2[0][z][offy] = bfpair(hz0, hz1);
    g_y2[1][z][offy] = bfpair(sz[0] - hz0, sz[1] - hz1);
}

// ---------------- scan pass 1: local chunk scan (dt_proj fused) ---------------
#define SROW 132
__global__ void __launch_bounds__(256) scan_p1(
    const float* __restrict__ Dv,
    const float* __restrict__ dtwA, const float* __restrict__ dtwB,
    const float* __restrict__ dtbA, const float* __restrict__ dtbB)
{
    __shared__ float sBt[32 * SROW];
    __shared__ float sCt[32 * SROW];
    __shared__ float sdt[32][33];
    __shared__ float swt[8][32];
    __shared__ float sdl[8][32];
    __shared__ float sdu[8][32];
    __shared__ float sr [8][32];

    int tid = threadIdx.x;
    int w = tid >> 5, lane = tid & 31;
    int chunk = blockIdx.y;
    int z = blockIdx.z, br = z >> 1;
    int d = blockIdx.x * 8 + w;

    float thrB = 0.1f * g_maxes[2 + br];
    float thrC = 0.1f * g_maxes[4 + br];
    const float* Arow = g_A + ((long)br * 256 + d) * 128;
    float a0 = Arow[4 * lane + 0] * LOG2EF;
    float a1 = Arow[4 * lane + 1] * LOG2EF;
    float a2 = Arow[4 * lane + 2] * LOG2EF;
    float a3 = Arow[4 * lane + 3] * LOG2EF;
    int   lin = g_lin[br * 256 + d];
    float d1p = g_D1[br * 256 + d] * LOG2EF;
    float Dd = Dv[d];
    float bias = (br ? dtbB : dtbA)[d];
    u64 h01 = 0ull, h23 = 0ull;
    float Ssum = 0.f;

    swt[w][lane] = ((br ? dtwB : dtwA))[d * 32 + lane];

    const float* Bbase  = g_xdbl + ((long)z * 288 + 32)  * LSEQ;
    const float* Cbase  = g_xdbl + ((long)z * 288 + 160) * LSEQ;
    const float* dtbase = g_xdbl + ((long)z * 288)       * LSEQ;
    const float* ubase  = g_xc   + ((long)z * 256 + d)   * LSEQ;
    float*       dlrow  = g_dl   + ((long)z * 256 + d)   * LSEQ;
    float*       ysrow  = g_ys   + ((long)z * 256 + d)   * LSEQ;

    for (int tile = 0; tile < 4; tile++) {
        int t0 = chunk * TCH + tile * 32;
        __syncthreads();
        #pragma unroll
        for (int cc = 0; cc < 4; cc++) {
            int lin2 = cc * 256 + tid;
            int n  = lin2 >> 3;
            int tq = (lin2 & 7) << 2;
            float4 v = *(const float4*)&Bbase[(long)n * LSEQ + t0 + tq];
            sBt[(tq + 0) * SROW + n] = spf(v.x, thrB);
            sBt[(tq + 1) * SROW + n] = spf(v.y, thrB);
            sBt[(tq + 2) * SROW + n] = spf(v.z, thrB);
            sBt[(tq + 3) * SROW + n] = spf(v.w, thrB);
            float4 c = *(const float4*)&Cbase[(long)n * LSEQ + t0 + tq];
            sCt[(tq + 0) * SROW + n] = spf(c.x, thrC);
            sCt[(tq + 1) * SROW + n] = spf(c.y, thrC);
            sCt[(tq + 2) * SROW + n] = spf(c.z, thrC);
            sCt[(tq + 3) * SROW + n] = spf(c.w, thrC);
        }
        {
            int row = tid >> 3;
            int tq  = (tid & 7) << 2;
            float4 v = *(const float4*)&dtbase[(long)row * LSEQ + t0 + tq];
            sdt[row][tq + 0] = v.x; sdt[row][tq + 1] = v.y;
            sdt[row][tq + 2] = v.z; sdt[row][tq + 3] = v.w;
        }
        __syncthreads();
        float uD;
        {
            float acc = bias;
            #pragma unroll
            for (int j = 0; j < 32; j++)
                acc = fmaf(swt[w][j], sdt[j][lane], acc);
            float delta = softplusf(acc);
            float uu = ubase[t0 + lane];
            sdl[w][lane] = delta;
            sdu[w][lane] = delta * uu;
            sr [w][lane] = ex2f(delta * d1p);
            uD = uu * Dd;
            dlrow[t0 + lane] = delta;
            float ts = delta;
            #pragma unroll
            for (int o = 16; o; o >>= 1) ts += __shfl_xor_sync(0xffffffffu, ts, o);
            Ssum += ts;
        }
        __syncthreads();

        float p[32];
        #pragma unroll
        for (int tt = 0; tt < 32; tt++) {
            float delta = sdl[w][tt];
            float du    = sdu[w][tt];
            float4 Bv = *(float4*)&sBt[tt * SROW + (lane << 2)];
            float4 Cv = *(float4*)&sCt[tt * SROW + (lane << 2)];
            float dA0, dA1, dA2, dA3;
            if (lin) {
                dA0 = ex2f(delta * a0);
                float r = sr[w][tt];
                dA1 = dA0 * r; dA2 = dA1 * r; dA3 = dA2 * r;
            } else {
                dA0 = ex2f(delta * a0); dA1 = ex2f(delta * a1);
                dA2 = ex2f(delta * a2); dA3 = ex2f(delta * a3);
            }
            u64 du2  = pk2(du, du);
            u64 b01  = pk2(Bv.x, Bv.y), b23 = pk2(Bv.z, Bv.w);
            u64 c01  = pk2(Cv.x, Cv.y), c23 = pk2(Cv.z, Cv.w);
            u64 dA01 = pk2(dA0, dA1), dA23 = pk2(dA2, dA3);
            h01 = fma2(dA01, h01, mul2(du2, b01));
            h23 = fma2(dA23, h23, mul2(du2, b23));
            u64 p2 = fma2(h23, c23, mul2(h01, c01));
            float plo, phi; upk2(p2, plo, phi);
            p[tt] = plo + phi;
        }

        #pragma unroll
        for (int mq = 16, len = 16; mq >= 1; mq >>= 1, len >>= 1) {
            bool hi = (lane & mq) != 0;
            #pragma unroll
            for (int i = 0; i < 16; i++) {
                if (i >= len) break;
                float send = hi ? p[i] : p[i + len];
                float recv = __shfl_xor_sync(0xffffffffu, send, mq);
                p[i] = (hi ? p[i + len] : p[i]) + recv;
            }
        }
        ysrow[t0 + lane] = p[0] + uD;
    }

    float h0f, h1f, h2f, h3f;
    upk2(h01, h0f, h1f); upk2(h23, h2f, h3f);
    long hidx = (((long)z * NCH + chunk) * 256 + d) * 128 + 4 * lane;
    *(float4*)&g_hloc[hidx] = make_float4(h0f, h1f, h2f, h3f);
    if (lane == 0) g_Ss[((long)z * 256 + d) * NCH + chunk] = Ssum;
}

// ---------------- scan pass 2: sequential chunk combine -----------------------
__global__ void __launch_bounds__(256) scan_p2() {
    int tid = threadIdx.x;
    int w = tid >> 5, lane = tid & 31;
    int z = blockIdx.y, br = z >> 1;
    int d = blockIdx.x * 8 + w;
    const float* Arow = g_A + ((long)br * 256 + d) * 128;
    float a0 = Arow[4 * lane + 0] * LOG2EF;
    float a1 = Arow[4 * lane + 1] * LOG2EF;
    float a2 = Arow[4 * lane + 2] * LOG2EF;
    float a3 = Arow[4 * lane + 3] * LOG2EF;
    float h0 = 0.f, h1 = 0.f, h2 = 0.f, h3 = 0.f;
    const float* Srow = g_Ss + ((long)z * 256 + d) * NCH;
    for (int c = 0; c < NCH; c++) {
        long hidx = (((long)z * NCH + c) * 256 + d) * 128 + 4 * lane;
        *(float4*)&g_hin[hidx] = make_float4(h0, h1, h2, h3);
        float4 hl = *(const float4*)&g_hloc[hidx];
        float S = Srow[c];
        h0 = fmaf(ex2f(a0 * S), h0, hl.x);
        h1 = fmaf(ex2f(a1 * S), h1, hl.y);
        h2 = fmaf(ex2f(a2 * S), h2, hl.z);
        h3 = fmaf(ex2f(a3 * S), h3, hl.w);
    }
}

// ---------------- scan pass 3: cross-chunk correction + bf16 pack -------------
__global__ void __launch_bounds__(256) scan_p3() {
    __shared__ float sCt[32 * SROW];
    __shared__ float spre[8][32];
    __shared__ float sy [8][32];

    int tid = threadIdx.x;
    int w = tid >> 5, lane = tid & 31;
    int chunk = blockIdx.y;
    int z = blockIdx.z, br = z >> 1;
    int d = blockIdx.x * 8 + w;

    float thrC = 0.1f * g_maxes[4 + br];
    const float* Arow = g_A + ((long)br * 256 + d) * 128;
    float a0 = Arow[4 * lane + 0] * LOG2EF;
    float a1 = Arow[4 * lane + 1] * LOG2EF;
    float a2 = Arow[4 * lane + 2] * LOG2EF;
    float a3 = Arow[4 * lane + 3] * LOG2EF;
    int   lin = g_lin[br * 256 + d];
    float d1p = g_D1[br * 256 + d] * LOG2EF;

    long hidx = (((long)z * NCH + chunk) * 256 + d) * 128 + 4 * lane;
    float4 hv = *(const float4*)&g_hin[hidx];

    const float* Cbase = g_xdbl + ((long)z * 288 + 160) * LSEQ;
    const float* dlrow = g_dl   + ((long)z * 256 + d)   * LSEQ;
    const float* ysrow = g_ys   + ((long)z * 256 + d)   * LSEQ;

    float Sbase = 0.f;

    for (int tile = 0; tile < 4; tile++) {
        int t0 = chunk * TCH + tile * 32;
        __syncthreads();
        #pragma unroll
        for (int cc = 0; cc < 4; cc++) {
            int lin2 = cc * 256 + tid;
            int n  = lin2 >> 3;
            int tq = (lin2 & 7) << 2;
            float4 c = *(const float4*)&Cbase[(long)n * LSEQ + t0 + tq];
            sCt[(tq + 0) * SROW + n] = spf(c.x, thrC);
            sCt[(tq + 1) * SROW + n] = spf(c.y, thrC);
            sCt[(tq + 2) * SROW + n] = spf(c.z, thrC);
            sCt[(tq + 3) * SROW + n] = spf(c.w, thrC);
        }
        float dl = dlrow[t0 + lane];
        float yv = ysrow[t0 + lane];
        float pre = dl;
        #pragma unroll
        for (int o = 1; o < 32; o <<= 1) {
            float v = __shfl_up_sync(0xffffffffu, pre, o);
            if (lane >= o) pre += v;
        }
        spre[w][lane] = Sbase + pre;
        Sbase += __shfl_sync(0xffffffffu, pre, 31);
        __syncthreads();

        float p[32];
        #pragma unroll
        for (int tt = 0; tt < 32; tt++) {
            float P = spre[w][tt];
            float4 Cv = *(float4*)&sCt[tt * SROW + (lane << 2)];
            float e0, e1, e2, e3;
            if (lin) {
                e0 = ex2f(P * a0);
                float r = ex2f(P * d1p);
                e1 = e0 * r; e2 = e1 * r; e3 = e2 * r;
            } else {
                e0 = ex2f(P * a0); e1 = ex2f(P * a1);
                e2 = ex2f(P * a2); e3 = ex2f(P * a3);
            }
            float q = (e0 * hv.x) * Cv.x;
            q = fmaf(e1 * hv.y, Cv.y, q);
            q = fmaf(e2 * hv.z, Cv.z, q);
            q = fmaf(e3 * hv.w, Cv.w, q);
            p[tt] = q;
        }

        #pragma unroll
        for (int mq = 16, len = 16; mq >= 1; mq >>= 1, len >>= 1) {
            bool hi = (lane & mq) != 0;
            #pragma unroll
            for (int i = 0; i < 16; i++) {
                if (i >= len) break;
                float send = hi ? p[i] : p[i + len];
                float recv = __shfl_xor_sync(0xffffffffu, send, mq);
                p[i] = (hi ? p[i + len] : p[i]) + recv;
            }
        }
        sy[w][lane] = yv + p[0];
        __syncthreads();
        if (tid < 128) {
            int p4 = tid >> 5, ll = tid & 31;
            float v0 = sy[2 * p4][ll], v1 = sy[2 * p4 + 1][ll];
            float h0 = bf16val(v0), h1 = bf16val(v1);
            long off = (long)(blockIdx.x * 4 + p4) * LSEQ + t0 + ll;
            g_y2[0][z][off] = bfpair(h0, h1);
            g_y2[1][z][off] = bfpair(v0 - h0, v1 - h1);
        }
    }
}

// ---------------- launch ------------------------------------------------------
extern "C" void kernel_launch(void* const* d_in, const int* in_sizes, int n_in,
                              void* d_out, int out_size) {
    const float* inp  = (const float*)d_in[0];
    const float* inw  = (const float*)d_in[1];
    const float* cxw  = (const float*)d_in[2];
    const float* czw  = (const float*)d_in[3];
    const float* xpw  = (const float*)d_in[4];
    const float* dtw  = (const float*)d_in[5];
    const float* dtb  = (const float*)d_in[6];
    const float* ow   = (const float*)d_in[7];
    const float* inw2 = (const float*)d_in[8];
    const float* cxw2 = (const float*)d_in[9];
    const float* czw2 = (const float*)d_in[10];
    const float* xpw2 = (const float*)d_in[11];
    const float* dtw2 = (const float*)d_in[12];
    const float* dtb2 = (const float*)d_in[13];
    const float* ow2  = (const float*)d_in[14];
    const float* Alog = (const float*)d_in[15];
    const float* Dv   = (const float*)d_in[16];
    const float* eps  = (const float*)d_in[17];
    float* out = (float*)d_out;

    float *p_xz, *p_xdbl;
    uint32_t *p_w2in, *p_w2xp, *p_w2out, *p_inp2, *p_xc2, *p_y2;
    cudaGetSymbolAddress((void**)&p_xz,    g_xz);
    cudaGetSymbolAddress((void**)&p_xdbl,  g_xdbl);
    cudaGetSymbolAddress((void**)&p_w2in,  g_w2in);
    cudaGetSymbolAddress((void**)&p_w2xp,  g_w2xp);
    cudaGetSymbolAddress((void**)&p_w2out, g_w2out);
    cudaGetSymbolAddress((void**)&p_inp2,  g_inp2);
    cudaGetSymbolAddress((void**)&p_xc2,   g_xc2);
    cudaGetSymbolAddress((void**)&p_y2,    g_y2);

    cudaFuncSetAttribute(gemm_cp<0>, cudaFuncAttributeMaxDynamicSharedMemorySize, G_SMEM_BYTES);
    cudaFuncSetAttribute(gemm_cp<1>, cudaFuncAttributeMaxDynamicSharedMemorySize, G_SMEM_BYTES);
    cudaFuncSetAttribute(gemm_cp<3>, cudaFuncAttributeMaxDynamicSharedMemorySize, G_SMEM_BYTES);

    const long L = LSEQ;

    cvt_w_m1<<<dim3(512, 7), 256>>>(inw, inw2, xpw, xpw2, ow, ow2, Alog, eps);
    cvt_inp_s1<<<8256, 256>>>(inp, Alog, eps);

    gemm_cp<0><<<dim3(16, 4, 4), 256, G_SMEM_BYTES>>>(
        p_w2in, 2L * 512 * 256, 512L * 256, 256,
        p_inp2, 256L * L, (long)NZ * 256 * L,
        p_xz, 512 * L, LSEQ, 512);

    conv_silu2<<<4162, 256>>>(cxw, czw, cxw2, czw2);

    gemm_cp<3><<<dim3(16, 3, 4), 256, G_SMEM_BYTES>>>(
        p_w2xp, 2L * 288 * 128, 288L * 128, 128,
        p_xc2, 128L * L, (long)NZ * 128 * L,
        p_xdbl, 288 * L, LSEQ, 288);

    scan_p1<<<dim3(32, NCH, 4), 256>>>(Dv, dtw, dtw2, dtb, dtb2);
    scan_p2<<<dim3(32, 4), 256>>>();
    scan_p3<<<dim3(32, NCH, 4), 256>>>();

    gemm_cp<1><<<dim3(16, 4, 4), 256, G_SMEM_BYTES>>>(
        p_w2out, 2L * 512 * 256, 512L * 256, 256,
        p_y2, 256L * L, (long)NZ * 256 * L,
        out, L * 512, 512, 512);
}

// round 16
// speedup vs baseline: 1.1138x; 1.1138x over previous
#include <cuda_runtime.h>
#include <cuda_bf16.h>
#include <math.h>
#include <stdint.h>

#define LSEQ 2048
#define NZ 4            // (branch, batch) pairs: z = br*2 + b
#define NCH 16          // scan chunks
#define TCH 128         // t per chunk

typedef unsigned long long u64;

// ---------------- scratch (device globals; no runtime allocation) ----------
__device__ float g_xz  [NZ * 512 * LSEQ];       // in_proj output [z][512][L]
__device__ float g_xc  [NZ * 256 * LSEQ];       // silu(conv(x)) fp32 (scan u)
__device__ float g_xdbl[NZ * 288 * LSEQ];       // x_proj output [z][288][L]
__device__ float g_A   [2 * 256 * 128];         // A1, A2
__device__ float g_maxes[8] = {
    -INFINITY, -INFINITY, -INFINITY, -INFINITY,
    -INFINITY, -INFINITY, -INFINITY, -INFINITY};
__device__ float g_D1  [2 * 256];
__device__ int   g_lin [2 * 256];

// chunked-scan intermediates
__device__ float g_dl  [NZ * 256 * LSEQ];       // delta
__device__ float g_ys  [NZ * 256 * LSEQ];       // local y (incl. u*D)
__device__ float g_hloc[NZ * NCH * 256 * 128];  // chunk-final local states
__device__ float g_hin [NZ * NCH * 256 * 128];  // chunk entry states
__device__ float g_Ss  [NZ * 256 * NCH];        // per-chunk sum of delta

// packed bf16 hi/lo operand planes  [plane][...]
__device__ uint32_t g_w2in [2][2][512 * 256];   // [br][plane][m*KP+kp]
__device__ uint32_t g_w2xp [2][2][288 * 128];
__device__ uint32_t g_w2out[2][2][512 * 256];
__device__ uint32_t g_inp2 [2][NZ][256 * 2048]; // [plane][z][kp*L+l]
__device__ uint32_t g_xc2  [2][NZ][128 * 2048];
__device__ uint32_t g_y2   [2][NZ][256 * 2048];

// ---------------- f32x2 packed helpers (scan) --------------------------------
__device__ __forceinline__ u64 pk2(float x, float y) {
    u64 r; asm("mov.b64 %0, {%1, %2};" : "=l"(r) : "f"(x), "f"(y)); return r;
}
__device__ __forceinline__ void upk2(u64 v, float& x, float& y) {
    asm("mov.b64 {%0, %1}, %2;" : "=f"(x), "=f"(y) : "l"(v));
}
__device__ __forceinline__ u64 fma2(u64 a, u64 b, u64 c) {
    u64 d; asm("fma.rn.f32x2 %0, %1, %2, %3;" : "=l"(d) : "l"(a), "l"(b), "l"(c));
    return d;
}
__device__ __forceinline__ u64 mul2(u64 a, u64 b) {
    u64 d; asm("mul.rn.f32x2 %0, %1, %2;" : "=l"(d) : "l"(a), "l"(b));
    return d;
}

// ---------------- scalar helpers ---------------------------------------------
__device__ __forceinline__ float spf(float v, float thr) {
    float a = fabsf(v) - thr;
    a = a > 0.f ? a : 0.f;
    return (v > 0.f) ? a : (v < 0.f ? -a : 0.f);
}
__device__ __forceinline__ float siluf(float v) { return v / (1.f + expf(-v)); }
__device__ __forceinline__ float softplusf(float v) {
    return (v > 20.f) ? v : log1pf(expf(v));
}
__device__ __forceinline__ float ex2f(float x) {
    float r; asm("ex2.approx.f32 %0, %1;" : "=f"(r) : "f"(x)); return r;
}
__device__ __forceinline__ float negInf() { return __int_as_float(0xff800000); }

__device__ float blockReduceMax(float v) {
    __shared__ float sh[32];
    __syncthreads();
    #pragma unroll
    for (int o = 16; o; o >>= 1) v = fmaxf(v, __shfl_xor_sync(0xffffffffu, v, o));
    if ((threadIdx.x & 31) == 0) sh[threadIdx.x >> 5] = v;
    __syncthreads();
    float r = negInf();
    if (threadIdx.x < (blockDim.x >> 5)) r = sh[threadIdx.x];
    if ((threadIdx.x >> 5) == 0) {
        #pragma unroll
        for (int o = 16; o; o >>= 1) r = fmaxf(r, __shfl_xor_sync(0xffffffffu, r, o));
        if (threadIdx.x == 0) sh[0] = r;
    }
    __syncthreads();
    return sh[0];
}

__device__ __forceinline__ void atomicMaxFloatCAS(float* addr, float val) {
    int* ai = (int*)addr;
    int old = *ai;
    while (__int_as_float(old) < val) {
        int assumed = old;
        old = atomicCAS(ai, assumed, __float_as_int(val));
        if (old == assumed) break;
    }
}

// ---------------- bf16 helpers -------------------------------------------------
__device__ __forceinline__ uint32_t bfpair(float x, float y) {
    __nv_bfloat162 h = __floats2bfloat162_rn(x, y);
    return *reinterpret_cast<uint32_t*>(&h);
}
__device__ __forceinline__ float bf16val(float x) {
    __nv_bfloat16 h = __float2bfloat16_rn(x);
    return __bfloat162float(h);
}

__device__ __forceinline__ void mma_bf16(float* d, const uint32_t* a, const uint32_t* b) {
    asm volatile(
        "mma.sync.aligned.m16n8k16.row.col.f32.bf16.bf16.f32 "
        "{%0,%1,%2,%3}, {%4,%5,%6,%7}, {%8,%9}, {%0,%1,%2,%3};"
        : "+f"(d[0]), "+f"(d[1]), "+f"(d[2]), "+f"(d[3])
        : "r"(a[0]), "r"(a[1]), "r"(a[2]), "r"(a[3]), "r"(b[0]), "r"(b[1]));
}

__device__ __forceinline__ void ldm_x4(uint32_t* r, uint32_t addr) {
    asm volatile(
        "ldmatrix.sync.aligned.m8n8.x4.shared.b16 {%0,%1,%2,%3}, [%4];"
        : "=r"(r[0]), "=r"(r[1]), "=r"(r[2]), "=r"(r[3]) : "r"(addr));
}

__device__ __forceinline__ uint32_t smem_u32(const void* p) {
    uint32_t a;
    asm("{ .reg .u64 t; cvta.to.shared.u64 t, %1; cvt.u32.u64 %0, t; }"
        : "=r"(a) : "l"(p));
    return a;
}
__device__ __forceinline__ void cpa16(uint32_t dst, const void* src) {
    asm volatile("cp.async.cg.shared.global [%0], [%1], 16;" :: "r"(dst), "l"(src));
}
#define CP_COMMIT() asm volatile("cp.async.commit_group;" ::: "memory")
#define CP_WAIT1()  asm volatile("cp.async.wait_group 1;" ::: "memory")
#define CP_WAIT0()  asm volatile("cp.async.wait_group 0;" ::: "memory")

// ---------------- weight conversion + prepA A-max (launch 1) ------------------
__global__ void cvt_w_m1(const float* __restrict__ inw,  const float* __restrict__ inw2,
                         const float* __restrict__ xpw,  const float* __restrict__ xpw2,
                         const float* __restrict__ ow,   const float* __restrict__ ow2,
                         const float* __restrict__ Alog, const float* __restrict__ eps) {
    int s = blockIdx.y;
    if (s == 6) {
        if (blockIdx.x >= 64) return;
        float e = 1.f + eps[0];
        float m = negInf();
        for (int i = blockIdx.x * blockDim.x + threadIdx.x; i < 256 * 128;
             i += 64 * blockDim.x)
            m = fmaxf(m, -e * expf(Alog[i]));
        m = blockReduceMax(m);
        if (threadIdx.x == 0) atomicMaxFloatCAS(&g_maxes[6], m);
        return;
    }
    int e = blockIdx.x * 256 + threadIdx.x;
    const float* src; uint32_t* dhi; uint32_t* dlo; int KP, total;
    if (s < 2)      { src = s        ? inw2 : inw; dhi = g_w2in [s][0];     dlo = g_w2in [s][1];     KP = 256; total = 512 * 256; }
    else if (s < 4) { src = (s - 2)  ? xpw2 : xpw; dhi = g_w2xp [s - 2][0]; dlo = g_w2xp [s - 2][1]; KP = 128; total = 288 * 128; }
    else            { src = (s - 4)  ? ow2  : ow;  dhi = g_w2out[s - 4][0]; dlo = g_w2out[s - 4][1]; KP = 256; total = 512 * 256; }
    if (e >= total) return;
    int m = e / KP, kp = e - m * KP;
    float v0 = src[(long)m * (KP * 2) + 2 * kp];
    float v1 = src[(long)m * (KP * 2) + 2 * kp + 1];
    float h0 = bf16val(v0), h1 = bf16val(v1);
    dhi[e] = bfpair(h0, h1);
    dlo[e] = bfpair(v0 - h0, v1 - h1);
}

// ---------------- input conversion + prepA stage 1 (launch 2) -----------------
__global__ void cvt_inp_s1(const float* __restrict__ inp,
                           const float* __restrict__ Alog,
                           const float* __restrict__ eps) {
    int bk = blockIdx.x;
    if (bk >= 8192) {
        int bx = bk - 8192;
        float e = 1.f + eps[0];
        float thr1 = 0.1f * g_maxes[6];
        float m = negInf();
        for (int i = bx * blockDim.x + threadIdx.x; i < 256 * 128;
             i += 64 * blockDim.x) {
            float a1 = spf(-e * expf(Alog[i]), thr1);
            g_A[i] = a1;
            m = fmaxf(m, a1);
        }
        m = blockReduceMax(m);
        if (threadIdx.x == 0) atomicMaxFloatCAS(&g_maxes[7], m);
        return;
    }
    long idx = (long)bk * blockDim.x + threadIdx.x;
    int l  = (int)(idx & 2047);
    int kp = (int)((idx >> 11) & 255);
    int z  = (int)(idx >> 19);
    int br = z >> 1, b = z & 1;
    const float* p = inp + ((long)b * 1024 + br * 512 + 2 * kp) * LSEQ + l;
    float v0 = p[0], v1 = p[LSEQ];
    float h0 = bf16val(v0), h1 = bf16val(v1);
    long off = (long)kp * LSEQ + l;
    g_inp2[0][z][off] = bfpair(h0, h1);
    g_inp2[1][z][off] = bfpair(v0 - h0, v1 - h1);
}

// ---------------- bf16-split tensor GEMM: 3-stage cp.async, 1 sync/chunk ------
#define G_SMEM_BYTES ((9216 + 6528) * 4)
template <int EPI>
__global__ void __launch_bounds__(256) gemm_cp(
    const uint32_t* __restrict__ W2, long wbr, long wpl, int KP,
    const uint32_t* __restrict__ B2, long bz, long bpl,
    float* __restrict__ C, long csz, int ldC, int M)
{
    extern __shared__ __align__(16) uint32_t smemU[];

    int z = blockIdx.z, br = z >> 1;
    const uint32_t* Wp = W2 + (long)br * wbr;
    const uint32_t* Bp = B2 + (long)z * bz;
    float*          Cp = C + (long)z * csz;
    int m0 = blockIdx.y * 128, n0 = blockIdx.x * 128;

    int tid = threadIdx.x;
    int wid = tid >> 5, lane = tid & 31;
    int g = lane >> 2, t = lane & 3;
    int wm = (wid >> 2) * 64;
    int wn = (wid & 3) * 32;

    int arow = tid >> 1, aseg = tid & 1;
    int am = m0 + arow; if (am >= M) am = M - 1;
    const uint32_t* aptr = Wp + (long)am * KP + aseg * 4;
    int bkp = tid >> 5, bseg = tid & 31;
    const uint32_t* bptr = Bp + (long)bkp * LSEQ + n0 + bseg * 4;

    uint32_t sAb = smem_u32(smemU);
    uint32_t sBb = sAb + 9216 * 4;
    uint32_t ldmOff = (uint32_t)((lane & 15) * 48 + (lane >> 4) * 16);

    float acc[4][4][4];
    #pragma unroll
    for (int i = 0; i < 4; i++)
        #pragma unroll
        for (int j = 0; j < 4; j++)
            #pragma unroll
            for (int q = 0; q < 4; q++) acc[i][j][q] = 0.f;

    const int NC = KP >> 3;

    auto issue = [&](int ic) {
        int buf = ic % 3;
        int kp0 = ic << 3;
        #pragma unroll
        for (int pl = 0; pl < 2; pl++) {
            cpa16(sAb + (uint32_t)(((buf * 2 + pl) * 1536 + arow * 12 + aseg * 4) * 4),
                  aptr + (long)pl * wpl + kp0);
            cpa16(sBb + (uint32_t)(((buf * 2 + pl) * 1088 + bkp * 136 + bseg * 4) * 4),
                  bptr + (long)pl * bpl + (long)kp0 * LSEQ);
        }
        CP_COMMIT();
    };

    issue(0);
    if (NC > 1) issue(1);

    for (int ic = 0; ic < NC; ic++) {
        if (ic + 1 < NC) { CP_WAIT1(); } else { CP_WAIT0(); }
        __syncthreads();
        if (ic + 2 < NC) issue(ic + 2);

        int s = ic % 3;
        const uint32_t* B0 = smemU + 9216 + (s * 2 + 0) * 1088;
        const uint32_t* B1 = smemU + 9216 + (s * 2 + 1) * 1088;
        uint32_t aHi = sAb + (uint32_t)((s * 2 + 0) * 1536 * 4) + (uint32_t)(wm * 48) + ldmOff;
        uint32_t aLo = sAb + (uint32_t)((s * 2 + 1) * 1536 * 4) + (uint32_t)(wm * 48) + ldmOff;

        uint32_t rbh[4][2], rbl[4][2];
        #pragma unroll
        for (int j = 0; j < 4; j++) {
            int nb = wn + 8 * j + g;
            rbh[j][0] = B0[t * 136 + nb];
            rbh[j][1] = B0[(t + 4) * 136 + nb];
            rbl[j][0] = B1[t * 136 + nb];
            rbl[j][1] = B1[(t + 4) * 136 + nb];
        }
        #pragma unroll
        for (int i = 0; i < 4; i++) {
            uint32_t rah[4], ral[4];
            ldm_x4(rah, aHi + (uint32_t)(i * 16 * 48));
            ldm_x4(ral, aLo + (uint32_t)(i * 16 * 48));
            #pragma unroll
            for (int j = 0; j < 4; j++) {
                mma_bf16(acc[i][j], rah, rbh[j]);
                mma_bf16(acc[i][j], rah, rbl[j]);
                mma_bf16(acc[i][j], ral, rbh[j]);
            }
        }
    }
    __syncthreads();

    if constexpr (EPI == 1) {
        float* sT = (float*)smemU;
        #pragma unroll
        for (int q = 0; q < 4; q++) {
            __syncthreads();
            if ((wid & 3) == q) {
                #pragma unroll
                for (int i = 0; i < 4; i++) {
                    #pragma unroll
                    for (int j = 0; j < 4; j++) {
                        int lloc = 8 * j + 2 * t;
                        int m1 = wm + 16 * i + g;
                        sT[lloc * 132 + m1]           = acc[i][j][0];
                        sT[(lloc + 1) * 132 + m1]     = acc[i][j][1];
                        sT[lloc * 132 + m1 + 8]       = acc[i][j][2];
                        sT[(lloc + 1) * 132 + m1 + 8] = acc[i][j][3];
                    }
                }
            }
            __syncthreads();
            int lloc = tid >> 3;
            int seg  = (tid & 7) * 16;
            long lg = n0 + q * 32 + lloc;
            float4*       dst  = (float4*)&Cp[lg * ldC + m0 + seg];
            const float4* srcp = (const float4*)&sT[lloc * 132 + seg];
            dst[0] = srcp[0]; dst[1] = srcp[1];
            dst[2] = srcp[2]; dst[3] = srcp[3];
        }
    } else {
        float mB = negInf(), mC = negInf();
        #pragma unroll
        for (int i = 0; i < 4; i++) {
            int m1 = m0 + wm + 16 * i + g;
            int m2 = m1 + 8;
            bool ok1 = m1 < M, ok2 = m2 < M;
            float r1mx = negInf(), r2mx = negInf();
            #pragma unroll
            for (int j = 0; j < 4; j++) {
                int l0 = n0 + wn + 8 * j + 2 * t;
                if (ok1) {
                    *(float2*)&Cp[(long)m1 * ldC + l0] =
                        make_float2(acc[i][j][0], acc[i][j][1]);
                    r1mx = fmaxf(r1mx, fmaxf(acc[i][j][0], acc[i][j][1]));
                }
                if (ok2) {
                    *(float2*)&Cp[(long)m2 * ldC + l0] =
                        make_float2(acc[i][j][2], acc[i][j][3]);
                    r2mx = fmaxf(r2mx, fmaxf(acc[i][j][2], acc[i][j][3]));
                }
            }
            if (EPI == 3) {
                if (ok1) {
                    if (m1 >= 32 && m1 < 160) mB = fmaxf(mB, r1mx);
                    else if (m1 >= 160)       mC = fmaxf(mC, r1mx);
                }
                if (ok2) {
                    if (m2 >= 32 && m2 < 160) mB = fmaxf(mB, r2mx);
                    else if (m2 >= 160)       mC = fmaxf(mC, r2mx);
                }
            }
        }
        if (EPI == 3) {
            #pragma unroll
            for (int o = 16; o; o >>= 1) {
                mB = fmaxf(mB, __shfl_xor_sync(0xffffffffu, mB, o));
                mC = fmaxf(mC, __shfl_xor_sync(0xffffffffu, mC, o));
            }
            if (lane == 0) {
                if (mB > negInf()) atomicMaxFloatCAS(&g_maxes[2 + br], mB);
                if (mC > negInf()) atomicMaxFloatCAS(&g_maxes[4 + br], mC);
            }
        }
    }
}

// ---------------- conv + silu, l-vectorized (+ fused prepA stage2/affine) -----
// blocks [0,1024): conv, thread = (z, d-pair, l-quad of 4)
// blocks [1024,1088): A2 materialize; [1088,1090): affine check
__device__ __forceinline__ void loadwin(const float* __restrict__ row, int l0, float* wv) {
    float4 a = *(const float4*)&row[l0];
    wv[0] = (l0 > 0) ? row[l0 - 1] : 0.f;
    wv[1] = a.x; wv[2] = a.y; wv[3] = a.z; wv[4] = a.w;
    if (l0 + 5 < LSEQ) {
        float2 b = *(const float2*)&row[l0 + 4];
        wv[5] = b.x; wv[6] = b.y;
    } else {
        wv[5] = 0.f; wv[6] = 0.f;
    }
}

__global__ void conv_silu2(const float* __restrict__ cxw0, const float* __restrict__ czw0,
                           const float* __restrict__ cxw1, const float* __restrict__ czw1) {
    int bk = blockIdx.x;
    if (bk >= 1024) {
        float thr2 = 0.1f * g_maxes[7];
        const int N = 256 * 128;
        int bx = bk - 1024;
        if (bx < 64) {
            for (int i = bx * blockDim.x + threadIdx.x; i < N;
                 i += 64 * blockDim.x)
                g_A[N + i] = spf(g_A[i], thr2);
            return;
        }
        int idx = (bx - 64) * blockDim.x + threadIdx.x;
        if (idx >= 512) return;
        bool isA2 = idx >= 256;
        const float* row = g_A + (long)(isA2 ? (idx - 256) : idx) * 128;
        float vprev = isA2 ? spf(row[0], thr2) : row[0];
        float v32   = isA2 ? spf(row[32], thr2) : row[32];
        float d1 = (v32 - vprev) * (1.f / 32.f);
        bool ok = true;
        for (int n = 1; n < 128; n++) {
            float v = isA2 ? spf(row[n], thr2) : row[n];
            ok = ok && (fabsf((v - vprev) - d1) <= 2e-4f);
            vprev = v;
        }
        g_D1[idx] = d1;
        g_lin[idx] = ok ? 1 : 0;
        return;
    }
    int idx = bk * 256 + threadIdx.x;      // 0 .. 262143
    int lq = idx & 511;
    int l0 = lq << 2;
    int p = (idx >> 9) & 127;
    int z = idx >> 16;
    int br = z >> 1;
    const float* cxw = br ? cxw1 : cxw0;
    const float* czw = br ? czw1 : czw0;

    float sx[2][4], sz[2][4];
    #pragma unroll
    for (int q = 0; q < 2; q++) {
        int d = 2 * p + q;
        const float* wx = cxw + d * 4;
        const float* wz = czw + d * 4;
        float wxx[4] = {wx[0], wx[1], wx[2], wx[3]};
        float wzz[4] = {wz[0], wz[1], wz[2], wz[3]};
        const float* xrow = g_xz + ((long)z * 512 + d) * LSEQ;
        const float* zrow = g_xz + ((long)z * 512 + 256 + d) * LSEQ;
        float wvx[7], wvz[7];
        loadwin(xrow, l0, wvx);
        loadwin(zrow, l0, wvz);
        #pragma unroll
        for (int ll = 0; ll < 4; ll++) {
            float ax = 0.f, az = 0.f;
            #pragma unroll
            for (int j = 0; j < 4; j++) {
                ax = fmaf(wxx[j], wvx[ll + j], ax);
                az = fmaf(wzz[j], wvz[ll + j], az);
            }
            sx[q][ll] = siluf(ax);
            sz[q][ll] = siluf(az);
        }
        // fp32 u row (coalesced float4)
        *(float4*)&g_xc[((long)z * 256 + d) * LSEQ + l0] =
            make_float4(sx[q][0], sx[q][1], sx[q][2], sx[q][3]);
    }
    // packed planes (uint4 along l)
    long off = (long)p * LSEQ + l0;
    uint32_t xh[4], xl[4], zh[4], zl[4];
    #pragma unroll
    for (int ll = 0; ll < 4; ll++) {
        float h0 = bf16val(sx[0][ll]), h1 = bf16val(sx[1][ll]);
        xh[ll] = bfpair(h0, h1);
        xl[ll] = bfpair(sx[0][ll] - h0, sx[1][ll] - h1);
        float g0 = bf16val(sz[0][ll]), g1 = bf16val(sz[1][ll]);
        zh[ll] = bfpair(g0, g1);
        zl[ll] = bfpair(sz[0][ll] - g0, sz[1][ll] - g1);
    }
    *(uint4*)&g_xc2[0][z][off] = make_uint4(xh[0], xh[1], xh[2], xh[3]);
    *(uint4*)&g_xc2[1][z][off] = make_uint4(xl[0], xl[1], xl[2], xl[3]);
    long offy = (long)(128 + p) * LSEQ + l0;
    *(uint4*)&g_y2[0][z][offy] = make_uint4(zh[0], zh[1], zh[2], zh[3]);
    *(uint4*)&g_y2[1][z][offy] = make_uint4(zl[0], zl[1], zl[2], zl[3]);
}

// ---------------- scan pass 1: local chunk scan (dt_proj fused) ---------------
#define SROW 132
__global__ void __launch_bounds__(256) scan_p1(
    const float* __restrict__ Dv,
    const float* __restrict__ dtwA, const float* __restrict__ dtwB,
    const float* __restrict__ dtbA, const float* __restrict__ dtbB)
{
    __shared__ float sBt[32 * SROW];
    __shared__ float sCt[32 * SROW];
    __shared__ float sdt[32][33];
    __shared__ float swt[8][32];
    __shared__ float sdl[8][32];
    __shared__ float sdu[8][32];
    __shared__ float sr [8][32];

    int tid = threadIdx.x;
    int w = tid >> 5, lane = tid & 31;
    int chunk = blockIdx.y;
    int z = blockIdx.z, br = z >> 1;
    int d = blockIdx.x * 8 + w;

    float thrB = 0.1f * g_maxes[2 + br];
    float thrC = 0.1f * g_maxes[4 + br];
    const float LOG2E = 1.4426950408889634f;
    const float* Arow = g_A + ((long)br * 256 + d) * 128;
    float a0 = Arow[4 * lane + 0] * LOG2E;
    float a1 = Arow[4 * lane + 1] * LOG2E;
    float a2 = Arow[4 * lane + 2] * LOG2E;
    float a3 = Arow[4 * lane + 3] * LOG2E;
    int   lin = g_lin[br * 256 + d];
    float d1p = g_D1[br * 256 + d] * LOG2E;
    float Dd = Dv[d];
    float bias = (br ? dtbB : dtbA)[d];
    u64 h01 = 0ull, h23 = 0ull;
    float Ssum = 0.f;

    swt[w][lane] = ((br ? dtwB : dtwA))[d * 32 + lane];

    const float* Bbase  = g_xdbl + ((long)z * 288 + 32)  * LSEQ;
    const float* Cbase  = g_xdbl + ((long)z * 288 + 160) * LSEQ;
    const float* dtbase = g_xdbl + ((long)z * 288)       * LSEQ;
    const float* ubase  = g_xc   + ((long)z * 256 + d)   * LSEQ;
    float*       dlrow  = g_dl   + ((long)z * 256 + d)   * LSEQ;
    float*       ysrow  = g_ys   + ((long)z * 256 + d)   * LSEQ;

    for (int tile = 0; tile < 4; tile++) {
        int t0 = chunk * TCH + tile * 32;
        __syncthreads();
        #pragma unroll
        for (int cc = 0; cc < 4; cc++) {
            int lin2 = cc * 256 + tid;
            int n  = lin2 >> 3;
            int tq = (lin2 & 7) << 2;
            float4 v = *(const float4*)&Bbase[(long)n * LSEQ + t0 + tq];
            sBt[(tq + 0) * SROW + n] = spf(v.x, thrB);
            sBt[(tq + 1) * SROW + n] = spf(v.y, thrB);
            sBt[(tq + 2) * SROW + n] = spf(v.z, thrB);
            sBt[(tq + 3) * SROW + n] = spf(v.w, thrB);
            float4 c = *(const float4*)&Cbase[(long)n * LSEQ + t0 + tq];
            sCt[(tq + 0) * SROW + n] = spf(c.x, thrC);
            sCt[(tq + 1) * SROW + n] = spf(c.y, thrC);
            sCt[(tq + 2) * SROW + n] = spf(c.z, thrC);
            sCt[(tq + 3) * SROW + n] = spf(c.w, thrC);
        }
        {
            int row = tid >> 3;
            int tq  = (tid & 7) << 2;
            float4 v = *(const float4*)&dtbase[(long)row * LSEQ + t0 + tq];
            sdt[row][tq + 0] = v.x; sdt[row][tq + 1] = v.y;
            sdt[row][tq + 2] = v.z; sdt[row][tq + 3] = v.w;
        }
        __syncthreads();
        float uD;
        {
            float acc = bias;
            #pragma unroll
            for (int j = 0; j < 32; j++)
                acc = fmaf(swt[w][j], sdt[j][lane], acc);
            float delta = softplusf(acc);
            float uu = ubase[t0 + lane];
            sdl[w][lane] = delta;
            sdu[w][lane] = delta * uu;
            sr [w][lane] = ex2f(delta * d1p);
            uD = uu * Dd;
            dlrow[t0 + lane] = delta;
            float ts = delta;
            #pragma unroll
            for (int o = 16; o; o >>= 1) ts += __shfl_xor_sync(0xffffffffu, ts, o);
            Ssum += ts;
        }
        __syncthreads();

        float p[32];
        #pragma unroll
        for (int tt = 0; tt < 32; tt++) {
            float delta = sdl[w][tt];
            float du    = sdu[w][tt];
            float4 Bv = *(float4*)&sBt[tt * SROW + (lane << 2)];
            float4 Cv = *(float4*)&sCt[tt * SROW + (lane << 2)];
            float dA0, dA1, dA2, dA3;
            if (lin) {
                dA0 = ex2f(delta * a0);
                float r = sr[w][tt];
                dA1 = dA0 * r; dA2 = dA1 * r; dA3 = dA2 * r;
            } else {
                dA0 = ex2f(delta * a0); dA1 = ex2f(delta * a1);
                dA2 = ex2f(delta * a2); dA3 = ex2f(delta * a3);
            }
            u64 du2  = pk2(du, du);
            u64 b01  = pk2(Bv.x, Bv.y), b23 = pk2(Bv.z, Bv.w);
            u64 c01  = pk2(Cv.x, Cv.y), c23 = pk2(Cv.z, Cv.w);
            u64 dA01 = pk2(dA0, dA1), dA23 = pk2(dA2, dA3);
            h01 = fma2(dA01, h01, mul2(du2, b01));
            h23 = fma2(dA23, h23, mul2(du2, b23));
            u64 p2 = fma2(h23, c23, mul2(h01, c01));
            float plo, phi; upk2(p2, plo, phi);
            p[tt] = plo + phi;
        }

        #pragma unroll
        for (int mq = 16, len = 16; mq >= 1; mq >>= 1, len >>= 1) {
            bool hi = (lane & mq) != 0;
            #pragma unroll
            for (int i = 0; i < 16; i++) {
                if (i >= len) break;
                float send = hi ? p[i] : p[i + len];
                float recv = __shfl_xor_sync(0xffffffffu, send, mq);
                p[i] = (hi ? p[i + len] : p[i]) + recv;
            }
        }
        ysrow[t0 + lane] = p[0] + uD;
    }

    float h0f, h1f, h2f, h3f;
    upk2(h01, h0f, h1f); upk2(h23, h2f, h3f);
    long hidx = (((long)z * NCH + chunk) * 256 + d) * 128 + 4 * lane;
    *(float4*)&g_hloc[hidx] = make_float4(h0f, h1f, h2f, h3f);
    if (lane == 0) g_Ss[((long)z * 256 + d) * NCH + chunk] = Ssum;
}

// ---------------- scan pass 2: sequential chunk combine -----------------------
__global__ void __launch_bounds__(256) scan_p2() {
    int tid = threadIdx.x;
    int w = tid >> 5, lane = tid & 31;
    int z = blockIdx.y, br = z >> 1;
    int d = blockIdx.x * 8 + w;
    const float LOG2E = 1.4426950408889634f;
    const float* Arow = g_A + ((long)br * 256 + d) * 128;
    float a0 = Arow[4 * lane + 0] * LOG2E;
    float a1 = Arow[4 * lane + 1] * LOG2E;
    float a2 = Arow[4 * lane + 2] * LOG2E;
    float a3 = Arow[4 * lane + 3] * LOG2E;
    float h0 = 0.f, h1 = 0.f, h2 = 0.f, h3 = 0.f;
    const float* Srow = g_Ss + ((long)z * 256 + d) * NCH;
    for (int c = 0; c < NCH; c++) {
        long hidx = (((long)z * NCH + c) * 256 + d) * 128 + 4 * lane;
        *(float4*)&g_hin[hidx] = make_float4(h0, h1, h2, h3);
        float4 hl = *(const float4*)&g_hloc[hidx];
        float S = Srow[c];
        h0 = fmaf(ex2f(a0 * S), h0, hl.x);
        h1 = fmaf(ex2f(a1 * S), h1, hl.y);
        h2 = fmaf(ex2f(a2 * S), h2, hl.z);
        h3 = fmaf(ex2f(a3 * S), h3, hl.w);
    }
}

// ---------------- scan pass 3: cross-chunk correction + bf16 pack -------------
__global__ void __launch_bounds__(256) scan_p3() {
    __shared__ float sCt[32 * SROW];
    __shared__ float spre[8][32];
    __shared__ float sy [8][32];

    int tid = threadIdx.x;
    int w = tid >> 5, lane = tid & 31;
    int chunk = blockIdx.y;
    int z = blockIdx.z, br = z >> 1;
    int d = blockIdx.x * 8 + w;

    float thrC = 0.1f * g_maxes[4 + br];
    const float LOG2E = 1.4426950408889634f;
    const float* Arow = g_A + ((long)br * 256 + d) * 128;
    float a0 = Arow[4 * lane + 0] * LOG2E;
    float a1 = Arow[4 * lane + 1] * LOG2E;
    float a2 = Arow[4 * lane + 2] * LOG2E;
    float a3 = Arow[4 * lane + 3] * LOG2E;
    int   lin = g_lin[br * 256 + d];
    float d1p = g_D1[br * 256 + d] * LOG2E;

    long hidx = (((long)z * NCH + chunk) * 256 + d) * 128 + 4 * lane;
    float4 hv = *(const float4*)&g_hin[hidx];

    const float* Cbase = g_xdbl + ((long)z * 288 + 160) * LSEQ;
    const float* dlrow = g_dl   + ((long)z * 256 + d)   * LSEQ;
    const float* ysrow = g_ys   + ((long)z * 256 + d)   * LSEQ;

    float Sbase = 0.f;

    for (int tile = 0; tile < 4; tile++) {
        int t0 = chunk * TCH + tile * 32;
        __syncthreads();
        #pragma unroll
        for (int cc = 0; cc < 4; cc++) {
            int lin2 = cc * 256 + tid;
            int n  = lin2 >> 3;
            int tq = (lin2 & 7) << 2;
            float4 c = *(const float4*)&Cbase[(long)n * LSEQ + t0 + tq];
            sCt[(tq + 0) * SROW + n] = spf(c.x, thrC);
            sCt[(tq + 1) * SROW + n] = spf(c.y, thrC);
            sCt[(tq + 2) * SROW + n] = spf(c.z, thrC);
            sCt[(tq + 3) * SROW + n] = spf(c.w, thrC);
        }
        float dl = dlrow[t0 + lane];
        float yv = ysrow[t0 + lane];
        float pre = dl;
        #pragma unroll
        for (int o = 1; o < 32; o <<= 1) {
            float v = __shfl_up_sync(0xffffffffu, pre, o);
            if (lane >= o) pre += v;
        }
        spre[w][lane] = Sbase + pre;
        Sbase += __shfl_sync(0xffffffffu, pre, 31);
        __syncthreads();

        float p[32];
        #pragma unroll
        for (int tt = 0; tt < 32; tt++) {
            float P = spre[w][tt];
            float4 Cv = *(float4*)&sCt[tt * SROW + (lane << 2)];
            float e0, e1, e2, e3;
            if (lin) {
                e0 = ex2f(P * a0);
                float r = ex2f(P * d1p);
                e1 = e0 * r; e2 = e1 * r; e3 = e2 * r;
            } else {
                e0 = ex2f(P * a0); e1 = ex2f(P * a1);
                e2 = ex2f(P * a2); e3 = ex2f(P * a3);
            }
            float q = (e0 * hv.x) * Cv.x;
            q = fmaf(e1 * hv.y, Cv.y, q);
            q = fmaf(e2 * hv.z, Cv.z, q);
            q = fmaf(e3 * hv.w, Cv.w, q);
            p[tt] = q;
        }

        #pragma unroll
        for (int mq = 16, len = 16; mq >= 1; mq >>= 1, len >>= 1) {
            bool hi = (lane & mq) != 0;
            #pragma unroll
            for (int i = 0; i < 16; i++) {
                if (i >= len) break;
                float send = hi ? p[i] : p[i + len];
                float recv = __shfl_xor_sync(0xffffffffu, send, mq);
                p[i] = (hi ? p[i + len] : p[i]) + recv;
            }
        }
        sy[w][lane] = yv + p[0];
        __syncthreads();
        if (tid < 128) {
            int p4 = tid >> 5, ll = tid & 31;
            float v0 = sy[2 * p4][ll], v1 = sy[2 * p4 + 1][ll];
            float h0 = bf16val(v0), h1 = bf16val(v1);
            long off = (long)(blockIdx.x * 4 + p4) * LSEQ + t0 + ll;
            g_y2[0][z][off] = bfpair(h0, h1);
            g_y2[1][z][off] = bfpair(v0 - h0, v1 - h1);
        }
    }
}

// ---------------- launch ------------------------------------------------------
extern "C" void kernel_launch(void* const* d_in, const int* in_sizes, int n_in,
                              void* d_out, int out_size) {
    const float* inp  = (const float*)d_in[0];
    const float* inw  = (const float*)d_in[1];
    const float* cxw  = (const float*)d_in[2];
    const float* czw  = (const float*)d_in[3];
    const float* xpw  = (const float*)d_in[4];
    const float* dtw  = (const float*)d_in[5];
    const float* dtb  = (const float*)d_in[6];
    const float* ow   = (const float*)d_in[7];
    const float* inw2 = (const float*)d_in[8];
    const float* cxw2 = (const float*)d_in[9];
    const float* czw2 = (const float*)d_in[10];
    const float* xpw2 = (const float*)d_in[11];
    const float* dtw2 = (const float*)d_in[12];
    const float* dtb2 = (const float*)d_in[13];
    const float* ow2  = (const float*)d_in[14];
    const float* Alog = (const float*)d_in[15];
    const float* Dv   = (const float*)d_in[16];
    const float* eps  = (const float*)d_in[17];
    float* out = (float*)d_out;

    float *p_xz, *p_xdbl;
    uint32_t *p_w2in, *p_w2xp, *p_w2out, *p_inp2, *p_xc2, *p_y2;
    cudaGetSymbolAddress((void**)&p_xz,    g_xz);
    cudaGetSymbolAddress((void**)&p_xdbl,  g_xdbl);
    cudaGetSymbolAddress((void**)&p_w2in,  g_w2in);
    cudaGetSymbolAddress((void**)&p_w2xp,  g_w2xp);
    cudaGetSymbolAddress((void**)&p_w2out, g_w2out);
    cudaGetSymbolAddress((void**)&p_inp2,  g_inp2);
    cudaGetSymbolAddress((void**)&p_xc2,   g_xc2);
    cudaGetSymbolAddress((void**)&p_y2,    g_y2);

    cudaFuncSetAttribute(gemm_cp<0>, cudaFuncAttributeMaxDynamicSharedMemorySize, G_SMEM_BYTES);
    cudaFuncSetAttribute(gemm_cp<1>, cudaFuncAttributeMaxDynamicSharedMemorySize, G_SMEM_BYTES);
    cudaFuncSetAttribute(gemm_cp<3>, cudaFuncAttributeMaxDynamicSharedMemorySize, G_SMEM_BYTES);

    const long L = LSEQ;

    cvt_w_m1<<<dim3(512, 7), 256>>>(inw, inw2, xpw, xpw2, ow, ow2, Alog, eps);
    cvt_inp_s1<<<8256, 256>>>(inp, Alog, eps);

    gemm_cp<0><<<dim3(16, 4, 4), 256, G_SMEM_BYTES>>>(
        p_w2in, 2L * 512 * 256, 512L * 256, 256,
        p_inp2, 256L * L, (long)NZ * 256 * L,
        p_xz, 512 * L, LSEQ, 512);

    conv_silu2<<<1090, 256>>>(cxw, czw, cxw2, czw2);

    gemm_cp<3><<<dim3(16, 3, 4), 256, G_SMEM_BYTES>>>(
        p_w2xp, 2L * 288 * 128, 288L * 128, 128,
        p_xc2, 128L * L, (long)NZ * 128 * L,
        p_xdbl, 288 * L, LSEQ, 288);

    scan_p1<<<dim3(32, NCH, 4), 256>>>(Dv, dtw, dtw2, dtb, dtb2);
    scan_p2<<<dim3(32, 4), 256>>>();
    scan_p3<<<dim3(32, NCH, 4), 256>>>();

    gemm_cp<1><<<dim3(16, 4, 4), 256, G_SMEM_BYTES>>>(
        p_w2out, 2L * 512 * 256, 512L * 256, 256,
        p_y2, 256L * L, (long)NZ * 256 * L,
        out, L * 512, 512, 512);
}